// round 1
// baseline (speedup 1.0000x reference)
#include <cuda_runtime.h>

#define BB 8
#define LL 2048
#define HH 8
#define EE 64
#define MM 64
#define LHALF 1024
#define NCHUNK 8

typedef unsigned long long ull;

// Scratch (device globals — no allocation allowed)
__device__ ull g_tw[LL];                      // packed (cos(2πk/L), -sin(2πk/L))
__device__ ull g_Xp[NCHUNK][BB*HH*MM*EE];     // forward partial sums, (Xr,Xi) pairs, [c][b][h][m][i]
__device__ ull g_Y[BB*HH*MM*EE];              // mixed+scaled modes, (Yr,Yi) pairs, [b][h][m][o]

__device__ __forceinline__ ull fma2(ull a, ull b, ull c) {
    ull d;
    asm("fma.rn.f32x2 %0, %1, %2, %3;" : "=l"(d) : "l"(a), "l"(b), "l"(c));
    return d;
}
__device__ __forceinline__ ull pack2(float x, float y) {
    ull r; asm("mov.b64 %0, {%1, %2};" : "=l"(r) : "f"(x), "f"(y)); return r;
}
__device__ __forceinline__ float2 unpack2(ull v) {
    float2 r; asm("mov.b64 {%0, %1}, %2;" : "=f"(r.x), "=f"(r.y) : "l"(v)); return r;
}

// ---------------------------------------------------------------------------
// Twiddle table: g_tw[k] = (cos(2πk/2048), -sin(2πk/2048))
// ---------------------------------------------------------------------------
__global__ void k_tw() {
    int k = blockIdx.x * blockDim.x + threadIdx.x;
    if (k < LL) {
        float s, c;
        sincospif((float)k * (1.0f / 1024.0f), &s, &c);
        g_tw[k] = pack2(c, -s);
    }
}

// ---------------------------------------------------------------------------
// Forward truncated DFT with radix-2 fold:
//   X_m = sum_{l<1024} w^{ml} * (m even ? x_l + x_{l+1024} : x_l - x_{l+1024})
// Block = (b, h, l-chunk c of 128). Thread tile: 4 i x 8 m.
// Accumulates (Xr, Xi) as packed f32x2: acc += (x,x) * (cos, -sin).
// ---------------------------------------------------------------------------
__global__ void __launch_bounds__(128) k_fwd(const float* __restrict__ x) {
    __shared__ ull   s_tw[LL];       // 16 KB
    __shared__ float s_u[64][EE];    // 16 KB  (x_l + x_{l+1024})
    __shared__ float s_v[64][EE];    // 16 KB  (x_l - x_{l+1024})
    const int tid = threadIdx.x;
    const int b = blockIdx.x >> 3, h = blockIdx.x & 7;
    const int c = blockIdx.y;

    for (int i = tid; i < LL; i += 128) s_tw[i] = g_tw[i];

    const int i0 = (tid & 15) * 4;
    const int m0 = (tid >> 4) * 8;   // multiple of 8 -> parity of (m0+j) is (j&1)

    ull acc[8][4];
    #pragma unroll
    for (int j = 0; j < 8; ++j) {
        #pragma unroll
        for (int k = 0; k < 4; ++k) acc[j][k] = 0ull;
    }

    const int lblk = c * 128;
    const float* xb = x + ((size_t)b * LL * HH + h) * EE;   // + l*(HH*EE) + i

    for (int stage = 0; stage < 2; ++stage) {
        const int lbase = lblk + stage * 64;
        __syncthreads();
        for (int idx4 = tid; idx4 < 64 * 16; idx4 += 128) {
            const int sl = idx4 >> 4;
            const int ii = (idx4 & 15) * 4;
            const float4 a = *(const float4*)&xb[(size_t)(lbase + sl) * (HH * EE) + ii];
            const float4 d = *(const float4*)&xb[(size_t)(lbase + sl + LHALF) * (HH * EE) + ii];
            *(float4*)&s_u[sl][ii] = make_float4(a.x + d.x, a.y + d.y, a.z + d.z, a.w + d.w);
            *(float4*)&s_v[sl][ii] = make_float4(a.x - d.x, a.y - d.y, a.z - d.z, a.w - d.w);
        }
        __syncthreads();
        #pragma unroll 2
        for (int sl = 0; sl < 64; ++sl) {
            const int l = lbase + sl;
            const float4 uu = *(const float4*)&s_u[sl][i0];
            const float4 vv = *(const float4*)&s_v[sl][i0];
            ull up[4], vp[4];
            up[0] = pack2(uu.x, uu.x); up[1] = pack2(uu.y, uu.y);
            up[2] = pack2(uu.z, uu.z); up[3] = pack2(uu.w, uu.w);
            vp[0] = pack2(vv.x, vv.x); vp[1] = pack2(vv.y, vv.y);
            vp[2] = pack2(vv.z, vv.z); vp[3] = pack2(vv.w, vv.w);
            #pragma unroll
            for (int j = 0; j < 8; ++j) {
                const ull tw = s_tw[((m0 + j) * l) & (LL - 1)];
                if (j & 1) {
                    acc[j][0] = fma2(vp[0], tw, acc[j][0]);
                    acc[j][1] = fma2(vp[1], tw, acc[j][1]);
                    acc[j][2] = fma2(vp[2], tw, acc[j][2]);
                    acc[j][3] = fma2(vp[3], tw, acc[j][3]);
                } else {
                    acc[j][0] = fma2(up[0], tw, acc[j][0]);
                    acc[j][1] = fma2(up[1], tw, acc[j][1]);
                    acc[j][2] = fma2(up[2], tw, acc[j][2]);
                    acc[j][3] = fma2(up[3], tw, acc[j][3]);
                }
            }
        }
    }

    ull* outp = &g_Xp[c][(((size_t)b * HH + h) * MM + m0) * EE + i0];
    #pragma unroll
    for (int j = 0; j < 8; ++j) {
        ull* p = outp + (size_t)j * EE;
        p[0] = acc[j][0]; p[1] = acc[j][1]; p[2] = acc[j][2]; p[3] = acc[j][3];
    }
}

// ---------------------------------------------------------------------------
// Mode mixing: out[b,o] = sum_i X[b,i] * (wr + i*wi)[h,i,o,m], per block (m,h).
// Also reduces the NCHUNK forward partials (fixed order -> deterministic) and
// folds the irfft weights: scale = (m==0 ? 1 : 2) / L.
// ---------------------------------------------------------------------------
__global__ void __launch_bounds__(128) k_mix(const float* __restrict__ wre,
                                             const float* __restrict__ wim) {
    __shared__ float sXr[BB][EE], sXi[BB][EE];   // 2 KB each
    __shared__ float sWr[EE][EE], sWi[EE][EE];   // 16 KB each
    const int m = blockIdx.x, h = blockIdx.y;
    const int tid = threadIdx.x;

    for (int idx = tid; idx < BB * EE; idx += 128) {
        const int b = idx >> 6, i = idx & 63;
        float xr = 0.f, xi = 0.f;
        const size_t off = (((size_t)b * HH + h) * MM + m) * EE + i;
        #pragma unroll
        for (int cc = 0; cc < NCHUNK; ++cc) {
            const float2 v = unpack2(g_Xp[cc][off]);
            xr += v.x; xi += v.y;
        }
        sXr[b][i] = xr; sXi[b][i] = xi;
    }
    const size_t wbase = (size_t)h * EE * EE * MM + m;
    for (int idx = tid; idx < EE * EE; idx += 128) {
        const int i = idx >> 6, o = idx & 63;
        const size_t off = wbase + ((size_t)i * EE + o) * MM;
        sWr[i][o] = wre[off];
        sWi[i][o] = wim[off];
    }
    __syncthreads();

    const int b = tid >> 4;
    const int o0 = (tid & 15) * 4;
    float ar0 = 0, ar1 = 0, ar2 = 0, ar3 = 0;
    float ai0 = 0, ai1 = 0, ai2 = 0, ai3 = 0;
    #pragma unroll 4
    for (int i = 0; i < EE; ++i) {
        const float xr = sXr[b][i], xi = sXi[b][i];
        const float4 w_r = *(const float4*)&sWr[i][o0];
        const float4 w_i = *(const float4*)&sWi[i][o0];
        ar0 = fmaf(xr, w_r.x, ar0); ar0 = fmaf(-xi, w_i.x, ar0);
        ai0 = fmaf(xr, w_i.x, ai0); ai0 = fmaf( xi, w_r.x, ai0);
        ar1 = fmaf(xr, w_r.y, ar1); ar1 = fmaf(-xi, w_i.y, ar1);
        ai1 = fmaf(xr, w_i.y, ai1); ai1 = fmaf( xi, w_r.y, ai1);
        ar2 = fmaf(xr, w_r.z, ar2); ar2 = fmaf(-xi, w_i.z, ar2);
        ai2 = fmaf(xr, w_i.z, ai2); ai2 = fmaf( xi, w_r.z, ai2);
        ar3 = fmaf(xr, w_r.w, ar3); ar3 = fmaf(-xi, w_i.w, ar3);
        ai3 = fmaf(xr, w_i.w, ai3); ai3 = fmaf( xi, w_r.w, ai3);
    }
    const float sc = (m == 0 ? 1.0f : 2.0f) * (1.0f / (float)LL);
    ull* dst = &g_Y[(((size_t)b * HH + h) * MM + m) * EE + o0];
    dst[0] = pack2(ar0 * sc, ai0 * sc);
    dst[1] = pack2(ar1 * sc, ai1 * sc);
    dst[2] = pack2(ar2 * sc, ai2 * sc);
    dst[3] = pack2(ar3 * sc, ai3 * sc);
}

// ---------------------------------------------------------------------------
// Inverse truncated DFT with radix-2 fold:
//   y_l       = E(l) + O(l),  y_{l+1024} = E(l) - O(l)
//   E(l) = sum_{m even} (Yr cos - Yi sin),  O(l) = sum_{m odd} (...)
// Pair trick: acc += (Yr,Yi)*(cos,-sin); final y = acc.lo + acc.hi.
// Block = (b, h, l-chunk c of 128). Thread tile: 2 l x 8 o.
// ---------------------------------------------------------------------------
__global__ void __launch_bounds__(128) k_inv(float* __restrict__ y) {
    __shared__ ull s_tw[LL];       // 16 KB
    __shared__ ull s_Y[MM * EE];   // 32 KB  [m][o] pairs
    const int tid = threadIdx.x;
    const int b = blockIdx.x >> 3, h = blockIdx.x & 7;
    const int c = blockIdx.y;

    for (int i = tid; i < LL; i += 128) s_tw[i] = g_tw[i];
    {
        const ull* src = &g_Y[((size_t)b * HH + h) * (MM * EE)];
        for (int i = tid; i < MM * EE; i += 128) s_Y[i] = src[i];
    }
    __syncthreads();

    const int o0 = (tid & 7) * 8;
    const int lg = tid >> 3;   // 0..15
    float* yb = y + ((size_t)b * LL * HH + h) * EE;

    for (int pass = 0; pass < 4; ++pass) {
        const int lA = c * 128 + pass * 32 + lg * 2;
        const int lB = lA + 1;
        ull ae[2][8], ao[2][8];
        #pragma unroll
        for (int k = 0; k < 8; ++k) { ae[0][k] = 0; ae[1][k] = 0; ao[0][k] = 0; ao[1][k] = 0; }

        int iA = 0, iB = 0;   // (m*l) & 2047 trackers
        for (int m = 0; m < MM; m += 2) {
            {   // even m -> ae
                const ull twA = s_tw[iA], twB = s_tw[iB];
                const ull* yp = &s_Y[(size_t)m * EE + o0];
                const ulonglong2 y01 = *(const ulonglong2*)(yp + 0);
                const ulonglong2 y23 = *(const ulonglong2*)(yp + 2);
                const ulonglong2 y45 = *(const ulonglong2*)(yp + 4);
                const ulonglong2 y67 = *(const ulonglong2*)(yp + 6);
                ae[0][0] = fma2(y01.x, twA, ae[0][0]); ae[1][0] = fma2(y01.x, twB, ae[1][0]);
                ae[0][1] = fma2(y01.y, twA, ae[0][1]); ae[1][1] = fma2(y01.y, twB, ae[1][1]);
                ae[0][2] = fma2(y23.x, twA, ae[0][2]); ae[1][2] = fma2(y23.x, twB, ae[1][2]);
                ae[0][3] = fma2(y23.y, twA, ae[0][3]); ae[1][3] = fma2(y23.y, twB, ae[1][3]);
                ae[0][4] = fma2(y45.x, twA, ae[0][4]); ae[1][4] = fma2(y45.x, twB, ae[1][4]);
                ae[0][5] = fma2(y45.y, twA, ae[0][5]); ae[1][5] = fma2(y45.y, twB, ae[1][5]);
                ae[0][6] = fma2(y67.x, twA, ae[0][6]); ae[1][6] = fma2(y67.x, twB, ae[1][6]);
                ae[0][7] = fma2(y67.y, twA, ae[0][7]); ae[1][7] = fma2(y67.y, twB, ae[1][7]);
                iA = (iA + lA) & (LL - 1);
                iB = (iB + lB) & (LL - 1);
            }
            {   // odd m+1 -> ao
                const ull twA = s_tw[iA], twB = s_tw[iB];
                const ull* yp = &s_Y[(size_t)(m + 1) * EE + o0];
                const ulonglong2 y01 = *(const ulonglong2*)(yp + 0);
                const ulonglong2 y23 = *(const ulonglong2*)(yp + 2);
                const ulonglong2 y45 = *(const ulonglong2*)(yp + 4);
                const ulonglong2 y67 = *(const ulonglong2*)(yp + 6);
                ao[0][0] = fma2(y01.x, twA, ao[0][0]); ao[1][0] = fma2(y01.x, twB, ao[1][0]);
                ao[0][1] = fma2(y01.y, twA, ao[0][1]); ao[1][1] = fma2(y01.y, twB, ao[1][1]);
                ao[0][2] = fma2(y23.x, twA, ao[0][2]); ao[1][2] = fma2(y23.x, twB, ao[1][2]);
                ao[0][3] = fma2(y23.y, twA, ao[0][3]); ao[1][3] = fma2(y23.y, twB, ao[1][3]);
                ao[0][4] = fma2(y45.x, twA, ao[0][4]); ao[1][4] = fma2(y45.x, twB, ao[1][4]);
                ao[0][5] = fma2(y45.y, twA, ao[0][5]); ao[1][5] = fma2(y45.y, twB, ao[1][5]);
                ao[0][6] = fma2(y67.x, twA, ao[0][6]); ao[1][6] = fma2(y67.x, twB, ao[1][6]);
                ao[0][7] = fma2(y67.y, twA, ao[0][7]); ao[1][7] = fma2(y67.y, twB, ao[1][7]);
                iA = (iA + lA) & (LL - 1);
                iB = (iB + lB) & (LL - 1);
            }
        }

        #pragma unroll
        for (int t = 0; t < 2; ++t) {
            const int l = lA + t;
            float se[8], so[8];
            #pragma unroll
            for (int k = 0; k < 8; ++k) {
                const float2 e = unpack2(ae[t][k]);
                const float2 o = unpack2(ao[t][k]);
                se[k] = e.x + e.y;
                so[k] = o.x + o.y;
            }
            const float4 lo0 = make_float4(se[0] + so[0], se[1] + so[1], se[2] + so[2], se[3] + so[3]);
            const float4 lo1 = make_float4(se[4] + so[4], se[5] + so[5], se[6] + so[6], se[7] + so[7]);
            const float4 hi0 = make_float4(se[0] - so[0], se[1] - so[1], se[2] - so[2], se[3] - so[3]);
            const float4 hi1 = make_float4(se[4] - so[4], se[5] - so[5], se[6] - so[6], se[7] - so[7]);
            *(float4*)&yb[(size_t)l * (HH * EE) + o0]                = lo0;
            *(float4*)&yb[(size_t)l * (HH * EE) + o0 + 4]            = lo1;
            *(float4*)&yb[(size_t)(l + LHALF) * (HH * EE) + o0]      = hi0;
            *(float4*)&yb[(size_t)(l + LHALF) * (HH * EE) + o0 + 4]  = hi1;
        }
    }
}

extern "C" void kernel_launch(void* const* d_in, const int* in_sizes, int n_in,
                              void* d_out, int out_size) {
    (void)in_sizes; (void)n_in; (void)out_size;
    const float* x   = (const float*)d_in[0];
    const float* wre = (const float*)d_in[1];
    const float* wim = (const float*)d_in[2];
    float* y = (float*)d_out;

    k_tw<<<2, 1024>>>();
    k_fwd<<<dim3(64, 8), 128>>>(x);
    k_mix<<<dim3(MM, HH), 128>>>(wre, wim);
    k_inv<<<dim3(64, 8), 128>>>(y);
}

// round 2
// speedup vs baseline: 1.5396x; 1.5396x over previous
#include <cuda_runtime.h>

#define BB 8
#define LL 2048
#define HH 8
#define EE 64
#define MM 64
#define LHALF 1024
#define NCHUNK 8

typedef unsigned long long ull;

// Scratch (device globals — no allocation allowed)
__device__ ull g_tw[LL];                      // packed (cos(2πk/L), -sin(2πk/L))
__device__ ull g_Xp[NCHUNK][BB*HH*MM*EE];     // forward partials, (Xr,Xi) pairs, [c][bh][m][i]
__device__ ull g_Y[BB*HH*MM*EE];              // mixed+scaled modes, (Yr,Yi) pairs, [bh][m][o]
__device__ float g_Wtr[HH*MM*EE*EE];          // transposed w_real: [h][m][i][o]
__device__ float g_Wti[HH*MM*EE*EE];          // transposed w_imag: [h][m][i][o]

__device__ __forceinline__ ull fma2(ull a, ull b, ull c) {
    ull d;
    asm("fma.rn.f32x2 %0, %1, %2, %3;" : "=l"(d) : "l"(a), "l"(b), "l"(c));
    return d;
}
__device__ __forceinline__ ull mul2(ull a, ull b) {
    ull d;
    asm("mul.rn.f32x2 %0, %1, %2;" : "=l"(d) : "l"(a), "l"(b));
    return d;
}
__device__ __forceinline__ ull pack2(float x, float y) {
    ull r; asm("mov.b64 %0, {%1, %2};" : "=l"(r) : "f"(x), "f"(y)); return r;
}
__device__ __forceinline__ float2 unpack2(ull v) {
    float2 r; asm("mov.b64 {%0, %1}, %2;" : "=f"(r.x), "=f"(r.y) : "l"(v)); return r;
}

// ---------------------------------------------------------------------------
// Twiddle table (forward kernel only): g_tw[k] = (cos(2πk/2048), -sin(2πk/2048))
// ---------------------------------------------------------------------------
__global__ void k_tw() {
    int k = blockIdx.x * blockDim.x + threadIdx.x;
    if (k < LL) {
        float s, c;
        sincospif((float)k * (1.0f / 1024.0f), &s, &c);
        g_tw[k] = pack2(c, -s);
    }
}

// ---------------------------------------------------------------------------
// W transpose: [h][i][o][m] -> [h][m][i][o]  (coalesced both sides via smem)
// Block = (h, i). 256 threads.
// ---------------------------------------------------------------------------
__global__ void __launch_bounds__(256) k_trans(const float* __restrict__ wre,
                                               const float* __restrict__ wim) {
    __shared__ float t[EE][EE + 1];
    const int h = blockIdx.x >> 6;
    const int i = blockIdx.x & 63;
    const int tid = threadIdx.x;
    const size_t in_base = (size_t)blockIdx.x * (EE * MM);     // ((h*64+i)*64+o)*64+m
    const size_t out_base = (size_t)h * (MM * EE * EE) + (size_t)i * EE;

    // real
    for (int idx = tid; idx < EE * MM; idx += 256) t[idx >> 6][idx & 63] = wre[in_base + idx];
    __syncthreads();
    for (int idx = tid; idx < MM * EE; idx += 256) {
        const int m = idx >> 6, o = idx & 63;
        g_Wtr[out_base + (size_t)m * (EE * EE) + o] = t[o][m];
    }
    __syncthreads();
    // imag
    for (int idx = tid; idx < EE * MM; idx += 256) t[idx >> 6][idx & 63] = wim[in_base + idx];
    __syncthreads();
    for (int idx = tid; idx < MM * EE; idx += 256) {
        const int m = idx >> 6, o = idx & 63;
        g_Wti[out_base + (size_t)m * (EE * EE) + o] = t[o][m];
    }
}

// ---------------------------------------------------------------------------
// Forward truncated DFT, radix-2 fold:
//   X_m = sum_{l<1024} tw^{ml} * (m even ? x_l + x_{l+1024} : x_l - x_{l+1024})
// Grid (bh=64, lchunk=8, mhalf=2). Block 128. Thread tile: 4 i x 4 m.
// ---------------------------------------------------------------------------
__global__ void __launch_bounds__(128) k_fwd(const float* __restrict__ x) {
    __shared__ ull   s_tw[LL];       // 16 KB
    __shared__ float s_u[32][EE];    // 8 KB
    __shared__ float s_v[32][EE];    // 8 KB
    const int tid = threadIdx.x;
    const int bh = blockIdx.x;
    const int b = bh >> 3, h = bh & 7;
    const int c = blockIdx.y;
    const int mh = blockIdx.z;

    for (int i = tid; i < LL; i += 128) s_tw[i] = g_tw[i];

    const int i0 = (tid & 15) * 4;
    const int m0 = mh * 32 + (tid >> 4) * 4;   // multiple of 4 -> parity(m0+j)=j&1

    ull acc[4][4];
    #pragma unroll
    for (int j = 0; j < 4; ++j)
        #pragma unroll
        for (int k = 0; k < 4; ++k) acc[j][k] = 0ull;

    const float* xb = x + ((size_t)b * LL * HH + h) * EE;

    for (int stage = 0; stage < 4; ++stage) {
        const int lbase = c * 128 + stage * 32;
        __syncthreads();
        for (int idx4 = tid; idx4 < 32 * 16; idx4 += 128) {
            const int sl = idx4 >> 4;
            const int ii = (idx4 & 15) * 4;
            const float4 a = *(const float4*)&xb[(size_t)(lbase + sl) * (HH * EE) + ii];
            const float4 d = *(const float4*)&xb[(size_t)(lbase + sl + LHALF) * (HH * EE) + ii];
            *(float4*)&s_u[sl][ii] = make_float4(a.x + d.x, a.y + d.y, a.z + d.z, a.w + d.w);
            *(float4*)&s_v[sl][ii] = make_float4(a.x - d.x, a.y - d.y, a.z - d.z, a.w - d.w);
        }
        __syncthreads();
        #pragma unroll 2
        for (int sl = 0; sl < 32; ++sl) {
            const int l = lbase + sl;
            const float4 uu = *(const float4*)&s_u[sl][i0];
            const float4 vv = *(const float4*)&s_v[sl][i0];
            ull up[4], vp[4];
            up[0] = pack2(uu.x, uu.x); up[1] = pack2(uu.y, uu.y);
            up[2] = pack2(uu.z, uu.z); up[3] = pack2(uu.w, uu.w);
            vp[0] = pack2(vv.x, vv.x); vp[1] = pack2(vv.y, vv.y);
            vp[2] = pack2(vv.z, vv.z); vp[3] = pack2(vv.w, vv.w);
            #pragma unroll
            for (int j = 0; j < 4; ++j) {
                const ull tw = s_tw[((m0 + j) * l) & (LL - 1)];
                if (j & 1) {
                    acc[j][0] = fma2(vp[0], tw, acc[j][0]);
                    acc[j][1] = fma2(vp[1], tw, acc[j][1]);
                    acc[j][2] = fma2(vp[2], tw, acc[j][2]);
                    acc[j][3] = fma2(vp[3], tw, acc[j][3]);
                } else {
                    acc[j][0] = fma2(up[0], tw, acc[j][0]);
                    acc[j][1] = fma2(up[1], tw, acc[j][1]);
                    acc[j][2] = fma2(up[2], tw, acc[j][2]);
                    acc[j][3] = fma2(up[3], tw, acc[j][3]);
                }
            }
        }
    }

    ull* outp = &g_Xp[c][(((size_t)bh) * MM + m0) * EE + i0];
    #pragma unroll
    for (int j = 0; j < 4; ++j) {
        ull* p = outp + (size_t)j * EE;
        p[0] = acc[j][0]; p[1] = acc[j][1]; p[2] = acc[j][2]; p[3] = acc[j][3];
    }
}

// ---------------------------------------------------------------------------
// Mode mixing per (m,h): reduce NCHUNK partials, complex GEMM over i, fold
// irfft scale (m==0?1:2)/L. W read from transposed (coalesced) layout.
// ---------------------------------------------------------------------------
__global__ void __launch_bounds__(128) k_mix() {
    __shared__ float sXr[BB][EE], sXi[BB][EE];
    __shared__ float sWr[EE][EE], sWi[EE][EE];
    const int m = blockIdx.x, h = blockIdx.y;
    const int tid = threadIdx.x;

    for (int idx = tid; idx < BB * EE; idx += 128) {
        const int b = idx >> 6, i = idx & 63;
        float xr = 0.f, xi = 0.f;
        const size_t off = (((size_t)(b * HH + h)) * MM + m) * EE + i;
        #pragma unroll
        for (int cc = 0; cc < NCHUNK; ++cc) {
            const float2 v = unpack2(g_Xp[cc][off]);
            xr += v.x; xi += v.y;
        }
        sXr[b][i] = xr; sXi[b][i] = xi;
    }
    const size_t wbase = ((size_t)h * MM + m) * (EE * EE);
    for (int idx = tid; idx < EE * EE; idx += 128) {
        sWr[idx >> 6][idx & 63] = g_Wtr[wbase + idx];
        sWi[idx >> 6][idx & 63] = g_Wti[wbase + idx];
    }
    __syncthreads();

    const int b = tid >> 4;
    const int o0 = (tid & 15) * 4;
    float ar0 = 0, ar1 = 0, ar2 = 0, ar3 = 0;
    float ai0 = 0, ai1 = 0, ai2 = 0, ai3 = 0;
    #pragma unroll 4
    for (int i = 0; i < EE; ++i) {
        const float xr = sXr[b][i], xi = sXi[b][i];
        const float4 w_r = *(const float4*)&sWr[i][o0];
        const float4 w_i = *(const float4*)&sWi[i][o0];
        ar0 = fmaf(xr, w_r.x, ar0); ar0 = fmaf(-xi, w_i.x, ar0);
        ai0 = fmaf(xr, w_i.x, ai0); ai0 = fmaf( xi, w_r.x, ai0);
        ar1 = fmaf(xr, w_r.y, ar1); ar1 = fmaf(-xi, w_i.y, ar1);
        ai1 = fmaf(xr, w_i.y, ai1); ai1 = fmaf( xi, w_r.y, ai1);
        ar2 = fmaf(xr, w_r.z, ar2); ar2 = fmaf(-xi, w_i.z, ar2);
        ai2 = fmaf(xr, w_i.z, ai2); ai2 = fmaf( xi, w_r.z, ai2);
        ar3 = fmaf(xr, w_r.w, ar3); ar3 = fmaf(-xi, w_i.w, ar3);
        ai3 = fmaf(xr, w_i.w, ai3); ai3 = fmaf( xi, w_r.w, ai3);
    }
    const float sc = (m == 0 ? 1.0f : 2.0f) * (1.0f / (float)LL);
    ull* dst = &g_Y[(((size_t)(b * HH + h)) * MM + m) * EE + o0];
    dst[0] = pack2(ar0 * sc, ai0 * sc);
    dst[1] = pack2(ar1 * sc, ai1 * sc);
    dst[2] = pack2(ar2 * sc, ai2 * sc);
    dst[3] = pack2(ar3 * sc, ai3 * sc);
}

// ---------------------------------------------------------------------------
// Inverse truncated DFT, radix-2 fold, register twiddle recurrence:
//   y_l = E(l)+O(l), y_{l+1024} = E(l)-O(l); tw(m+1,l) = tw(m,l) * w^l
// Grid (bh=64, lchunk=8, ohalf=2). Block 128. Thread: 2 l x 4 o, 4 passes.
// ---------------------------------------------------------------------------
__global__ void __launch_bounds__(128) k_inv(float* __restrict__ y) {
    __shared__ ull s_Y[MM * 32];   // 16 KB: [m][o-half 32]
    const int tid = threadIdx.x;
    const int bh = blockIdx.x;
    const int b = bh >> 3, h = bh & 7;
    const int lc = blockIdx.y;
    const int oh = blockIdx.z;

    {
        const ull* src = &g_Y[(size_t)bh * (MM * EE) + oh * 32];
        for (int idx = tid; idx < MM * 32; idx += 128)
            s_Y[idx] = src[(idx >> 5) * EE + (idx & 31)];
    }
    __syncthreads();

    const int og = tid & 7;
    const int o0 = og * 4;            // local in half
    const int lg = tid >> 3;          // 0..15
    const int o_g = oh * 32 + o0;     // global o
    float* yb = y + ((size_t)b * LL * HH + h) * EE + o_g;

    for (int pass = 0; pass < 4; ++pass) {
        const int lA = lc * 128 + pass * 32 + lg * 2;
        const int lB = lA + 1;

        // w^l = (cos(pi*l/1024), -sin(pi*l/1024)); P=(wr,wi), Q=(-wi,wr)
        float sA, cA, sB, cB;
        sincospif((float)lA * (1.0f / 1024.0f), &sA, &cA);
        sincospif((float)lB * (1.0f / 1024.0f), &sB, &cB);
        const ull PA = pack2(cA, -sA), QA = pack2(sA, cA);
        const ull PB = pack2(cB, -sB), QB = pack2(sB, cB);

        ull twA = pack2(1.0f, 0.0f), twB = pack2(1.0f, 0.0f);
        ull aeA[4], aoA[4], aeB[4], aoB[4];
        #pragma unroll
        for (int k = 0; k < 4; ++k) { aeA[k] = 0; aoA[k] = 0; aeB[k] = 0; aoB[k] = 0; }

        #pragma unroll 4
        for (int m = 0; m < MM; m += 2) {
            {   // even m
                const ulonglong2 y01 = *(const ulonglong2*)&s_Y[m * 32 + o0];
                const ulonglong2 y23 = *(const ulonglong2*)&s_Y[m * 32 + o0 + 2];
                aeA[0] = fma2(y01.x, twA, aeA[0]); aeB[0] = fma2(y01.x, twB, aeB[0]);
                aeA[1] = fma2(y01.y, twA, aeA[1]); aeB[1] = fma2(y01.y, twB, aeB[1]);
                aeA[2] = fma2(y23.x, twA, aeA[2]); aeB[2] = fma2(y23.x, twB, aeB[2]);
                aeA[3] = fma2(y23.y, twA, aeA[3]); aeB[3] = fma2(y23.y, twB, aeB[3]);
                const float2 tA = unpack2(twA);
                twA = fma2(pack2(tA.x, tA.x), PA, mul2(pack2(tA.y, tA.y), QA));
                const float2 tB = unpack2(twB);
                twB = fma2(pack2(tB.x, tB.x), PB, mul2(pack2(tB.y, tB.y), QB));
            }
            {   // odd m+1
                const ulonglong2 y01 = *(const ulonglong2*)&s_Y[(m + 1) * 32 + o0];
                const ulonglong2 y23 = *(const ulonglong2*)&s_Y[(m + 1) * 32 + o0 + 2];
                aoA[0] = fma2(y01.x, twA, aoA[0]); aoB[0] = fma2(y01.x, twB, aoB[0]);
                aoA[1] = fma2(y01.y, twA, aoA[1]); aoB[1] = fma2(y01.y, twB, aoB[1]);
                aoA[2] = fma2(y23.x, twA, aoA[2]); aoB[2] = fma2(y23.x, twB, aoB[2]);
                aoA[3] = fma2(y23.y, twA, aoA[3]); aoB[3] = fma2(y23.y, twB, aoB[3]);
                const float2 tA = unpack2(twA);
                twA = fma2(pack2(tA.x, tA.x), PA, mul2(pack2(tA.y, tA.y), QA));
                const float2 tB = unpack2(twB);
                twB = fma2(pack2(tB.x, tB.x), PB, mul2(pack2(tB.y, tB.y), QB));
            }
        }

        // combine + store (lA, lB) x (low, high half)
        {
            float se[4], so[4];
            #pragma unroll
            for (int k = 0; k < 4; ++k) {
                const float2 e = unpack2(aeA[k]); const float2 o = unpack2(aoA[k]);
                se[k] = e.x + e.y; so[k] = o.x + o.y;
            }
            *(float4*)&yb[(size_t)lA * (HH * EE)] =
                make_float4(se[0] + so[0], se[1] + so[1], se[2] + so[2], se[3] + so[3]);
            *(float4*)&yb[(size_t)(lA + LHALF) * (HH * EE)] =
                make_float4(se[0] - so[0], se[1] - so[1], se[2] - so[2], se[3] - so[3]);
        }
        {
            float se[4], so[4];
            #pragma unroll
            for (int k = 0; k < 4; ++k) {
                const float2 e = unpack2(aeB[k]); const float2 o = unpack2(aoB[k]);
                se[k] = e.x + e.y; so[k] = o.x + o.y;
            }
            *(float4*)&yb[(size_t)lB * (HH * EE)] =
                make_float4(se[0] + so[0], se[1] + so[1], se[2] + so[2], se[3] + so[3]);
            *(float4*)&yb[(size_t)(lB + LHALF) * (HH * EE)] =
                make_float4(se[0] - so[0], se[1] - so[1], se[2] - so[2], se[3] - so[3]);
        }
    }
}

extern "C" void kernel_launch(void* const* d_in, const int* in_sizes, int n_in,
                              void* d_out, int out_size) {
    (void)in_sizes; (void)n_in; (void)out_size;
    const float* x   = (const float*)d_in[0];
    const float* wre = (const float*)d_in[1];
    const float* wim = (const float*)d_in[2];
    float* y = (float*)d_out;

    k_tw<<<2, 1024>>>();
    k_trans<<<512, 256>>>(wre, wim);
    k_fwd<<<dim3(64, 8, 2), 128>>>(x);
    k_mix<<<dim3(MM, HH), 128>>>();
    k_inv<<<dim3(64, 8, 2), 128>>>(y);
}